// round 4
// baseline (speedup 1.0000x reference)
#include <cuda_runtime.h>
#include <cuda_bf16.h>
#include <math.h>

#define BB 32
#define CC 512
#define HW 1024
#define DD 64
#define OO 640   // 2*D + C

// ---------------- scratch (device globals) ----------------
__device__ float g_qkv[BB * OO * HW];            // 80 MB (tf32-rounded Q,K,V)
__device__ float g_beta[(size_t)BB * HW * HW];   // 128 MB (raw S)
__device__ float g_xr[BB * CC * HW];             // 64 MB
__device__ float g_h[BB * CC * HW];              // 64 MB (h1)
__device__ float g_vt[BB * CC * HW];             // 64 MB (Vt)
__device__ float g_z[BB * CC * HW];              // 64 MB (mlp hidden)
__device__ float g_wqkvt[CC * OO];
__device__ float g_w1t[CC * CC];
__device__ float g_w2t[CC * CC];
__device__ float g_b1f[CC];
__device__ float g_scale1[CC], g_shift1[CC], g_scale2[CC], g_shift2[CC];
__device__ float g_pmax[BB * 8 * HW], g_psum[BB * 8 * HW];
__device__ float g_cmax[BB * HW], g_cinv[BB * HW];

// ---------------- helpers ----------------
__device__ __forceinline__ float fexp(float x) {
    x = fmaxf(x, -87.0f);
    float t  = x * 1.4426950408889634f;
    float fi = floorf(t);
    float f  = t - fi;
    float r = 1.5403530e-4f;
    r = fmaf(r, f, 1.3333558e-3f);
    r = fmaf(r, f, 9.6181291e-3f);
    r = fmaf(r, f, 5.5504109e-2f);
    r = fmaf(r, f, 2.4022651e-1f);
    r = fmaf(r, f, 6.9314718e-1f);
    r = fmaf(r, f, 1.0f);
    return r * __int_as_float(((int)fi + 127) << 23);
}

__device__ __forceinline__ float rtf(float x) {
    unsigned u;
    asm("cvt.rna.tf32.f32 %0, %1;" : "=r"(u) : "f"(x));
    return __uint_as_float(u);
}

__device__ __forceinline__ void cpa16(void* s, const void* g) {
    unsigned ss = (unsigned)__cvta_generic_to_shared(s);
    asm volatile("cp.async.cg.shared.global [%0], [%1], 16;\n" :: "r"(ss), "l"(g));
}

__device__ __forceinline__ void mma8(float* c, const unsigned* a, const unsigned* b) {
    asm volatile(
        "mma.sync.aligned.m16n8k8.row.col.f32.tf32.tf32.f32 "
        "{%0,%1,%2,%3}, {%4,%5,%6,%7}, {%8,%9}, {%0,%1,%2,%3};\n"
        : "+f"(c[0]), "+f"(c[1]), "+f"(c[2]), "+f"(c[3])
        : "r"(a[0]), "r"(a[1]), "r"(a[2]), "r"(a[3]), "r"(b[0]), "r"(b[1]));
}

// ---------------- bn stats ----------------
__global__ void bn_stats_kernel(const float* __restrict__ x,
                                const float* __restrict__ gamma,
                                const float* __restrict__ beta,
                                float* __restrict__ scale,
                                float* __restrict__ shift) {
    int c = blockIdx.x;
    int tid = threadIdx.x;
    float s = 0.f, s2 = 0.f;
    const float* xc = x + (size_t)c * HW;
    for (int b = 0; b < BB; b++) {
        const float* p = xc + (size_t)b * CC * HW;
        #pragma unroll 4
        for (int i = tid; i < HW; i += 256) {
            float v = p[i];
            s += v; s2 = fmaf(v, v, s2);
        }
    }
    __shared__ float ss[256], ss2[256];
    ss[tid] = s; ss2[tid] = s2;
    __syncthreads();
    for (int o = 128; o > 0; o >>= 1) {
        if (tid < o) { ss[tid] += ss[tid + o]; ss2[tid] += ss2[tid + o]; }
        __syncthreads();
    }
    if (tid == 0) {
        const float invN = 1.0f / (BB * HW);
        float mean = ss[0] * invN;
        float var  = ss2[0] * invN - mean * mean;
        float sc = gamma[c] * rsqrtf(var + 1e-5f);
        scale[c] = sc;
        shift[c] = beta[c] - mean * sc;
    }
}

// ---------------- bn1 apply + relu, tf32-rounded ----------------
__global__ void bn_apply_relu(const float* __restrict__ x, const float* __restrict__ sc,
                              const float* __restrict__ sh, float* __restrict__ o) {
    int i = blockIdx.x * 256 + threadIdx.x;
    int c = (i >> 8) & (CC - 1);
    float4 v = ((const float4*)x)[i];
    float s = sc[c], h = sh[c];
    v.x = rtf(fmaxf(fmaf(v.x, s, h), 0.f));
    v.y = rtf(fmaxf(fmaf(v.y, s, h), 0.f));
    v.z = rtf(fmaxf(fmaf(v.z, s, h), 0.f));
    v.w = rtf(fmaxf(fmaf(v.w, s, h), 0.f));
    ((float4*)o)[i] = v;
}

// ---------------- fold bn2 into W1 ----------------
__global__ void w1_fold(const float* __restrict__ W1, const float* __restrict__ b1,
                        const float* __restrict__ sc, const float* __restrict__ sh,
                        float* __restrict__ w1t, float* __restrict__ b1f) {
    int o = blockIdx.x;
    int tid = threadIdx.x;
    float acc = 0.f;
    for (int k = tid; k < CC; k += 256) {
        float w = W1[o * CC + k];
        acc = fmaf(w, sh[k], acc);
        w1t[k * CC + o] = rtf(w * sc[k]);
    }
    __shared__ float r[256];
    r[tid] = acc; __syncthreads();
    for (int ofs = 128; ofs > 0; ofs >>= 1) {
        if (tid < ofs) r[tid] += r[tid + ofs];
        __syncthreads();
    }
    if (tid == 0) b1f[o] = b1[o] + r[0];
}

// ---------------- transpose (+tf32 round), batched ----------------
__global__ void transpose_rnd(const float* __restrict__ in, float* __restrict__ out,
                              int rows, int cols, long sIn, long sOut) {
    __shared__ float t[32][33];
    int z = blockIdx.z;
    const float* I = in + (size_t)z * sIn;
    float* O = out + (size_t)z * sOut;
    int c0 = blockIdx.x * 32, r0 = blockIdx.y * 32;
    int x = threadIdx.x, y = threadIdx.y;
    #pragma unroll
    for (int j = 0; j < 32; j += 8)
        t[y + j][x] = I[(size_t)(r0 + y + j) * cols + c0 + x];
    __syncthreads();
    #pragma unroll
    for (int j = 0; j < 32; j += 8)
        O[(size_t)(c0 + y + j) * rows + r0 + x] = rtf(t[x][y + j]);
}

// ---------------- combine 8 per-qtile softmax partials ----------------
__global__ void softmax_combine8(const float* __restrict__ pmax,
                                 const float* __restrict__ psum,
                                 float* __restrict__ cmax, float* __restrict__ cinv) {
    int b = blockIdx.y;
    int k = blockIdx.x * 256 + threadIdx.x;
    float m = -3.0e38f, s = 0.f;
    #pragma unroll
    for (int qt = 0; qt < 8; qt++) {
        size_t o = ((size_t)(b * 8 + qt) << 10) + k;
        float mv = pmax[o], sv = psum[o];
        float nm = fmaxf(m, mv);
        s = fmaf(s, fexp(m - nm), sv * fexp(mv - nm));
        m = nm;
    }
    cmax[(b << 10) + k] = m;
    cinv[(b << 10) + k] = 1.0f / s;
}

// ---------------- tf32 tensor-core GEMM ----------------
// C[m,n] = alpha*sum_k A[k,m]*B[k,n] (+ fused epilogue/B-transform)
#define F_EBIAS  1
#define F_ERELU  2
#define F_ERES   4
#define F_EROUND 8
#define F_STAT   16
// BM: 0 = cp.async B; 1 = LDG-staged B with rtf; 2 = LDG-staged B with exp(S-max)*inv then rtf

#define ASTR 136
#define BSTR 264
#define ASTAGE (16 * ASTR)
#define BSTAGE (16 * BSTR)
#define SMEM_T ((2 * ASTAGE + 2 * BSTAGE + 512) * 4)

template <int F, int BM>
__global__ void __launch_bounds__(256, 1) tgemm(
    const float* __restrict__ A, const float* __restrict__ B, float* __restrict__ C,
    int M, int N, int K, int lda, int ldb, int ldc,
    long sA, long sB, long sC,
    const float* __restrict__ bias,
    const float* __restrict__ res, long sRes,
    const float* __restrict__ cmax, const float* __restrict__ cinv,
    float* __restrict__ pmax, float* __restrict__ psum,
    float alpha)
{
    extern __shared__ float sm[];
    float* As = sm;
    float* Bs = sm + 2 * ASTAGE;
    float* cs_m = sm + 2 * ASTAGE + 2 * BSTAGE;
    float* cs_i = cs_m + 256;

    const int bz = blockIdx.z;
    const int n0 = blockIdx.x * 256;
    const int m0 = blockIdx.y * 128;
    const int tid = threadIdx.x;
    const int warp = tid >> 5;
    const int lane = tid & 31;
    const int wm = warp & 1;
    const int wn = warp >> 1;
    const int g = lane >> 2;
    const int tg = lane & 3;

    const float* Ab = A + (size_t)bz * sA;
    const float* Bb = B + (size_t)bz * sB;

    if (BM == 2) {
        if (tid < 256) {
            cs_m[tid] = cmax[(size_t)bz * N + n0 + tid];
            cs_i[tid] = cinv[(size_t)bz * N + n0 + tid];
        }
    }

    float acc[4][8][4];
    #pragma unroll
    for (int i = 0; i < 4; i++)
        #pragma unroll
        for (int j = 0; j < 8; j++)
            #pragma unroll
            for (int r = 0; r < 4; r++) acc[i][j][r] = 0.f;

    float4 Breg[4];

    auto loadA = [&](int st, int k0) {
        float* Ad = As + st * ASTAGE;
        #pragma unroll
        for (int j = 0; j < 2; j++) {
            int id = tid + j * 256;
            int k = id >> 5, m4 = (id & 31) << 2;
            cpa16(Ad + k * ASTR + m4, Ab + (size_t)(k0 + k) * lda + m0 + m4);
        }
    };
    auto loadBcp = [&](int st, int k0) {
        float* Bd = Bs + st * BSTAGE;
        #pragma unroll
        for (int j = 0; j < 4; j++) {
            int id = tid + j * 256;
            int k = id >> 6, n4 = (id & 63) << 2;
            cpa16(Bd + k * BSTR + n4, Bb + (size_t)(k0 + k) * ldb + n0 + n4);
        }
    };
    auto ldB = [&](int k0) {
        #pragma unroll
        for (int j = 0; j < 4; j++) {
            int id = tid + j * 256;
            int k = id >> 6, n4 = (id & 63) << 2;
            Breg[j] = *(const float4*)(Bb + (size_t)(k0 + k) * ldb + n0 + n4);
        }
    };
    auto stB = [&](int st) {
        float* Bd = Bs + st * BSTAGE;
        #pragma unroll
        for (int j = 0; j < 4; j++) {
            int id = tid + j * 256;
            int k = id >> 6, n4 = (id & 63) << 2;
            float4 v = Breg[j];
            if (BM == 2) {
                v.x = rtf(fexp(v.x - cs_m[n4 + 0]) * cs_i[n4 + 0]);
                v.y = rtf(fexp(v.y - cs_m[n4 + 1]) * cs_i[n4 + 1]);
                v.z = rtf(fexp(v.z - cs_m[n4 + 2]) * cs_i[n4 + 2]);
                v.w = rtf(fexp(v.w - cs_m[n4 + 3]) * cs_i[n4 + 3]);
            } else {
                v.x = rtf(v.x); v.y = rtf(v.y); v.z = rtf(v.z); v.w = rtf(v.w);
            }
            *(float4*)&Bd[k * BSTR + n4] = v;
        }
    };

    auto mmaStage = [&](int st) {
        const float* Asb = As + st * ASTAGE;
        const float* Bsb = Bs + st * BSTAGE;
        #pragma unroll
        for (int kk = 0; kk < 16; kk += 8) {
            unsigned a[4][4], bfr[8][2];
            const int r0 = kk + tg;
            #pragma unroll
            for (int mi = 0; mi < 4; mi++) {
                int m = wm * 64 + mi * 16 + g;
                a[mi][0] = __float_as_uint(Asb[r0 * ASTR + m]);
                a[mi][1] = __float_as_uint(Asb[r0 * ASTR + m + 8]);
                a[mi][2] = __float_as_uint(Asb[(r0 + 4) * ASTR + m]);
                a[mi][3] = __float_as_uint(Asb[(r0 + 4) * ASTR + m + 8]);
            }
            #pragma unroll
            for (int ni = 0; ni < 8; ni++) {
                int n = wn * 64 + ni * 8 + g;
                bfr[ni][0] = __float_as_uint(Bsb[r0 * BSTR + n]);
                bfr[ni][1] = __float_as_uint(Bsb[(r0 + 4) * BSTR + n]);
            }
            #pragma unroll
            for (int mi = 0; mi < 4; mi++)
                #pragma unroll
                for (int ni = 0; ni < 8; ni++)
                    mma8(acc[mi][ni], a[mi], bfr[ni]);
        }
    };

    const int T = K >> 4;
    if (BM == 0) {
        loadA(0, 0); loadBcp(0, 0);
        asm volatile("cp.async.commit_group;\n");
        for (int t = 0; t < T; t++) {
            if (t + 1 < T) {
                loadA((t + 1) & 1, (t + 1) << 4);
                loadBcp((t + 1) & 1, (t + 1) << 4);
                asm volatile("cp.async.commit_group;\n");
                asm volatile("cp.async.wait_group 1;\n");
            } else {
                asm volatile("cp.async.wait_group 0;\n");
            }
            __syncthreads();
            mmaStage(t & 1);
            __syncthreads();
        }
    } else {
        loadA(0, 0);
        asm volatile("cp.async.commit_group;\n");
        ldB(0);
        __syncthreads();                       // cs_m/cs_i visible
        asm volatile("cp.async.wait_group 0;\n");
        stB(0);
        __syncthreads();
        for (int t = 0; t < T; t++) {
            if (t + 1 < T) {
                loadA((t + 1) & 1, (t + 1) << 4);
                asm volatile("cp.async.commit_group;\n");
                ldB((t + 1) << 4);
            }
            mmaStage(t & 1);
            if (t + 1 < T) {
                asm volatile("cp.async.wait_group 0;\n");
                stB((t + 1) & 1);
            }
            __syncthreads();
        }
    }

    // ---------------- epilogue: write C ----------------
    float* Cb = C + (size_t)bz * sC;
    const float* Rb = (F & F_ERES) ? (res + (size_t)bz * sRes) : nullptr;
    #pragma unroll
    for (int mi = 0; mi < 4; mi++) {
        int mr = m0 + wm * 64 + mi * 16 + g;
        float bi0 = 0.f, bi8 = 0.f;
        if (F & F_EBIAS) { bi0 = bias[mr]; bi8 = bias[mr + 8]; }
        #pragma unroll
        for (int ni = 0; ni < 8; ni++) {
            int nc = n0 + wn * 64 + ni * 8 + tg * 2;
            float v0 = acc[mi][ni][0] * alpha + bi0;
            float v1 = acc[mi][ni][1] * alpha + bi0;
            float v2 = acc[mi][ni][2] * alpha + bi8;
            float v3 = acc[mi][ni][3] * alpha + bi8;
            if (F & F_ERES) {
                float2 rA = *(const float2*)(Rb + (size_t)mr * ldc + nc);
                float2 rB = *(const float2*)(Rb + (size_t)(mr + 8) * ldc + nc);
                v0 += rA.x; v1 += rA.y; v2 += rB.x; v3 += rB.y;
            }
            if (F & F_ERELU) {
                v0 = fmaxf(v0, 0.f); v1 = fmaxf(v1, 0.f);
                v2 = fmaxf(v2, 0.f); v3 = fmaxf(v3, 0.f);
            }
            if (F & F_EROUND) {
                v0 = rtf(v0); v1 = rtf(v1); v2 = rtf(v2); v3 = rtf(v3);
            }
            *(float2*)(Cb + (size_t)mr * ldc + nc) = make_float2(v0, v1);
            *(float2*)(Cb + (size_t)(mr + 8) * ldc + nc) = make_float2(v2, v3);
        }
    }

    // ---------------- fused softmax column stats (S-GEMM only) ----------------
    if (F & F_STAT) {
        float ms[16], ssv[16];
        #pragma unroll
        for (int ni = 0; ni < 8; ni++) {
            #pragma unroll
            for (int jj = 0; jj < 2; jj++) {
                int idx = ni * 2 + jj;
                float ml = -3.0e38f;
                #pragma unroll
                for (int mi = 0; mi < 4; mi++) {
                    ml = fmaxf(ml, acc[mi][ni][jj] * alpha);
                    ml = fmaxf(ml, acc[mi][ni][jj + 2] * alpha);
                }
                float sl = 0.f;
                #pragma unroll
                for (int mi = 0; mi < 4; mi++) {
                    sl += fexp(acc[mi][ni][jj] * alpha - ml);
                    sl += fexp(acc[mi][ni][jj + 2] * alpha - ml);
                }
                ms[idx] = ml; ssv[idx] = sl;
            }
        }
        #pragma unroll
        for (int ofs = 4; ofs <= 16; ofs <<= 1) {
            #pragma unroll
            for (int idx = 0; idx < 16; idx++) {
                float mo = __shfl_xor_sync(0xffffffffu, ms[idx], ofs);
                float so = __shfl_xor_sync(0xffffffffu, ssv[idx], ofs);
                float nm = fmaxf(ms[idx], mo);
                ssv[idx] = ssv[idx] * fexp(ms[idx] - nm) + so * fexp(mo - nm);
                ms[idx] = nm;
            }
        }
        __syncthreads();
        float2* wst = (float2*)sm;   // [wm][wn][64]
        if (g == 0) {
            #pragma unroll
            for (int ni = 0; ni < 8; ni++)
                #pragma unroll
                for (int jj = 0; jj < 2; jj++) {
                    int col = ni * 8 + tg * 2 + jj;
                    wst[(wm * 4 + wn) * 64 + col] = make_float2(ms[ni * 2 + jj], ssv[ni * 2 + jj]);
                }
        }
        __syncthreads();
        if (wm == 0) {
            #pragma unroll
            for (int cjj = 0; cjj < 2; cjj++) {
                int col = lane * 2 + cjj;
                float2 p0 = wst[(0 * 4 + wn) * 64 + col];
                float2 p1 = wst[(1 * 4 + wn) * 64 + col];
                float nm = fmaxf(p0.x, p1.x);
                float s = p0.y * fexp(p0.x - nm) + p1.y * fexp(p1.x - nm);
                size_t o = ((size_t)(bz * 8 + blockIdx.y) << 10) + n0 + wn * 64 + col;
                pmax[o] = nm; psum[o] = s;
            }
        }
    }
}

// ---------------- launcher ----------------
extern "C" void kernel_launch(void* const* d_in, const int* in_sizes, int n_in,
                              void* d_out, int out_size) {
    const float* x     = (const float*)d_in[0];
    const float* bn1_g = (const float*)d_in[1];
    const float* bn1_b = (const float*)d_in[2];
    const float* W_qkv = (const float*)d_in[3];
    const float* b_qkv = (const float*)d_in[4];
    const float* bn2_g = (const float*)d_in[5];
    const float* bn2_b = (const float*)d_in[6];
    const float* W1    = (const float*)d_in[7];
    const float* b1    = (const float*)d_in[8];
    const float* W2    = (const float*)d_in[9];
    const float* b2    = (const float*)d_in[10];
    float* out = (float*)d_out;

    float *p_qkv, *p_beta, *p_xr, *p_h, *p_vt, *p_z;
    float *p_wqkvt, *p_w1t, *p_w2t, *p_b1f;
    float *p_s1, *p_h1, *p_s2, *p_h2;
    float *p_pmax, *p_psum, *p_cmax, *p_cinv;
    cudaGetSymbolAddress((void**)&p_qkv,   g_qkv);
    cudaGetSymbolAddress((void**)&p_beta,  g_beta);
    cudaGetSymbolAddress((void**)&p_xr,    g_xr);
    cudaGetSymbolAddress((void**)&p_h,     g_h);
    cudaGetSymbolAddress((void**)&p_vt,    g_vt);
    cudaGetSymbolAddress((void**)&p_z,     g_z);
    cudaGetSymbolAddress((void**)&p_wqkvt, g_wqkvt);
    cudaGetSymbolAddress((void**)&p_w1t,   g_w1t);
    cudaGetSymbolAddress((void**)&p_w2t,   g_w2t);
    cudaGetSymbolAddress((void**)&p_b1f,   g_b1f);
    cudaGetSymbolAddress((void**)&p_s1,    g_scale1);
    cudaGetSymbolAddress((void**)&p_h1,    g_shift1);
    cudaGetSymbolAddress((void**)&p_s2,    g_scale2);
    cudaGetSymbolAddress((void**)&p_h2,    g_shift2);
    cudaGetSymbolAddress((void**)&p_pmax,  g_pmax);
    cudaGetSymbolAddress((void**)&p_psum,  g_psum);
    cudaGetSymbolAddress((void**)&p_cmax,  g_cmax);
    cudaGetSymbolAddress((void**)&p_cinv,  g_cinv);

    cudaFuncSetAttribute(tgemm<F_EBIAS | F_EROUND, 0>, cudaFuncAttributeMaxDynamicSharedMemorySize, SMEM_T);
    cudaFuncSetAttribute(tgemm<F_STAT, 0>,             cudaFuncAttributeMaxDynamicSharedMemorySize, SMEM_T);
    cudaFuncSetAttribute(tgemm<F_ERES, 2>,             cudaFuncAttributeMaxDynamicSharedMemorySize, SMEM_T);
    cudaFuncSetAttribute(tgemm<F_EBIAS | F_ERELU | F_EROUND, 1>, cudaFuncAttributeMaxDynamicSharedMemorySize, SMEM_T);
    cudaFuncSetAttribute(tgemm<F_EBIAS | F_ERES, 0>,   cudaFuncAttributeMaxDynamicSharedMemorySize, SMEM_T);

    const long sX = (long)CC * HW;
    const long sQ = (long)OO * HW;
    const long sS = (long)HW * HW;

    // 0) weight transposes (+tf32 round); W1 handled by fold later
    transpose_rnd<<<dim3(16, 20, 1), dim3(32, 8)>>>(W_qkv, p_wqkvt, OO, CC, 0, 0);
    transpose_rnd<<<dim3(16, 16, 1), dim3(32, 8)>>>(W2, p_w2t, CC, CC, 0, 0);

    // 1) bn1 stats + h1 = rtf(relu(bn1(x)))
    bn_stats_kernel<<<CC, 256>>>(x, bn1_g, bn1_b, p_s1, p_h1);
    bn_apply_relu<<<BB * CC * HW / 4 / 256, 256>>>(x, p_s1, p_h1, p_h);

    // 2) qkv = Wqkv @ h1 + b_qkv (rounded)
    tgemm<F_EBIAS | F_EROUND, 0><<<dim3(4, 5, BB), 256, SMEM_T>>>(
        p_wqkvt, p_h, p_qkv, OO, HW, CC, OO, HW, HW,
        0L, sX, sQ, b_qkv, nullptr, 0L, nullptr, nullptr, nullptr, nullptr, 1.0f);

    // 3) S = (Q^T K)/8 + fused per-qtile column softmax stats
    tgemm<F_STAT, 0><<<dim3(4, 8, BB), 256, SMEM_T>>>(
        p_qkv, p_qkv + DD * HW, p_beta, HW, HW, DD, HW, HW, HW,
        sQ, sQ, sS, nullptr, nullptr, 0L, nullptr, nullptr, p_pmax, p_psum, 0.125f);

    // 4) combine stats
    softmax_combine8<<<dim3(4, BB), 256>>>(p_pmax, p_psum, p_cmax, p_cinv);

    // 5) Vt = rtf(V^T)
    transpose_rnd<<<dim3(32, 16, BB), dim3(32, 8)>>>(
        p_qkv + 2 * DD * HW, p_vt, CC, HW, sQ, sX);

    // 6) xr = x + Vt^T P  (P generated on the fly from raw S)
    tgemm<F_ERES, 2><<<dim3(4, 4, BB), 256, SMEM_T>>>(
        p_vt, p_beta, p_xr, CC, HW, HW, CC, HW, HW,
        sX, sS, sX, nullptr, x, sX, p_cmax, p_cinv, nullptr, nullptr, 1.0f);

    // 7) bn2 stats + fold into W1
    bn_stats_kernel<<<CC, 256>>>(p_xr, bn2_g, bn2_b, p_s2, p_h2);
    w1_fold<<<CC, 256>>>(W1, b1, p_s2, p_h2, p_w1t, p_b1f);

    // 8) z = rtf(relu(W1' @ xr + b1'))  (B=xr rounded in staging)
    tgemm<F_EBIAS | F_ERELU | F_EROUND, 1><<<dim3(4, 4, BB), 256, SMEM_T>>>(
        p_w1t, p_xr, p_z, CC, HW, CC, CC, HW, HW,
        0L, sX, sX, p_b1f, nullptr, 0L, nullptr, nullptr, nullptr, nullptr, 1.0f);

    // 9) out = xr + W2 @ z + b2
    tgemm<F_EBIAS | F_ERES, 0><<<dim3(4, 4, BB), 256, SMEM_T>>>(
        p_w2t, p_z, out, CC, HW, CC, CC, HW, HW,
        0L, sX, sX, b2, p_xr, sX, nullptr, nullptr, nullptr, nullptr, 1.0f);
}

// round 8
// speedup vs baseline: 1.6621x; 1.6621x over previous
#include <cuda_runtime.h>
#include <cuda_fp16.h>
#include <math.h>
#include <stdint.h>

#define BB 32
#define CC 512
#define HW 1024
#define DD 64
#define OO 640

// ---------------- scratch (device globals) ----------------
__device__ __half g_ht[(size_t)BB * HW * CC];    // h1^T [b][hw][c]
__device__ __half g_qkt[(size_t)BB * HW * OO];   // [b][hw][o]: q 0:64, k 64:128, v^T 128:640
__device__ __half g_v[(size_t)BB * CC * HW];     // V [b][c][hw]
__device__ __half g_st[(size_t)BB * HW * HW];    // S^T then P^T [b][k'][q]
__device__ float  g_xr[(size_t)BB * CC * HW];    // xr fp32 [b][c][hw]
__device__ __half g_xrt[(size_t)BB * HW * CC];   // xr^T half [b][hw][c]
__device__ __half g_zt[(size_t)BB * HW * CC];    // z^T [b][hw][o]
__device__ __half g_wqh[OO * CC];                // W_qkv half [o][c]
__device__ __half g_w1f[CC * CC];                // (W1*bn2sc) half [o][c]
__device__ __half g_w2h[CC * CC];                // W2 half [c][o]
__device__ float  g_b1f[CC];
__device__ float  g_s1[CC], g_h1[CC], g_s2[CC], g_h2[CC];

// ---------------- helpers ----------------
__device__ __forceinline__ float fexp(float x) {
    x = fmaxf(x, -87.0f);
    float t  = x * 1.4426950408889634f;
    float fi = floorf(t);
    float f  = t - fi;
    float r = 1.5403530e-4f;
    r = fmaf(r, f, 1.3333558e-3f);
    r = fmaf(r, f, 9.6181291e-3f);
    r = fmaf(r, f, 5.5504109e-2f);
    r = fmaf(r, f, 2.4022651e-1f);
    r = fmaf(r, f, 6.9314718e-1f);
    r = fmaf(r, f, 1.0f);
    return r * __int_as_float(((int)fi + 127) << 23);
}
__device__ __forceinline__ void cpa16(void* s, const void* g) {
    unsigned ss = (unsigned)__cvta_generic_to_shared(s);
    asm volatile("cp.async.cg.shared.global [%0], [%1], 16;\n" :: "r"(ss), "l"(g));
}
__device__ __forceinline__ void mma16(float* c, const uint32_t* a, const uint32_t* b) {
    asm volatile(
        "mma.sync.aligned.m16n8k16.row.col.f32.f16.f16.f32 "
        "{%0,%1,%2,%3}, {%4,%5,%6,%7}, {%8,%9}, {%0,%1,%2,%3};\n"
        : "+f"(c[0]), "+f"(c[1]), "+f"(c[2]), "+f"(c[3])
        : "r"(a[0]), "r"(a[1]), "r"(a[2]), "r"(a[3]), "r"(b[0]), "r"(b[1]));
}
__device__ __forceinline__ void ldsm4(uint32_t* r, uint32_t addr) {
    asm volatile("ldmatrix.sync.aligned.m8n8.x4.shared.b16 {%0,%1,%2,%3}, [%4];"
        : "=r"(r[0]), "=r"(r[1]), "=r"(r[2]), "=r"(r[3]) : "r"(addr));
}
__device__ __forceinline__ void ldsm2(uint32_t* r, uint32_t addr) {
    asm volatile("ldmatrix.sync.aligned.m8n8.x2.shared.b16 {%0,%1}, [%2];"
        : "=r"(r[0]), "=r"(r[1]) : "r"(addr));
}

// ---------------- fp16 tensor GEMM ----------------
// C[m,n] = alpha * sum_k A[m][k] * B[n][k]  (A row-major, B n-major, both k-contig half)
// CTA: 128(M) x NT(N), 8 warps, k-stage 32, 2-stage cp.async double buffer.
// EPI: 0 = half store + bias[n]
//      1 = half store * alpha
//      2 = fp32 store + res
//      3 = half store + bias[n] + relu
//      4 = fp32 store + bias[m] + res
#define RSTR 40                    // 32 + 8 halves pad (80B row, 16B-aligned)
#define ASTG (128 * RSTR)

template <int NT, int EPI>
__global__ void __launch_bounds__(256, 1) hgemm(
    const __half* __restrict__ A, const __half* __restrict__ B, void* __restrict__ Cv,
    int K, int lda, int ldb, int ldc,
    long sA, long sB, long sC,
    const float* __restrict__ bias,
    const float* __restrict__ res, long sRes,
    float alpha)
{
    constexpr int BSTG = NT * RSTR;
    constexpr int NF = (NT == 256) ? 8 : 4;   // n-frags per warp
    constexpr int WNW = (NT == 256) ? 64 : 32;

    extern __shared__ __align__(16) __half smh[];
    __half* As = smh;                  // 2 stages
    __half* Bs = smh + 2 * ASTG;

    const int bz = blockIdx.z;
    const int n0 = blockIdx.x * NT;
    const int m0 = blockIdx.y * 128;
    const int tid = threadIdx.x;
    const int warp = tid >> 5;
    const int lane = tid & 31;
    const int wm = warp & 1;
    const int wn = warp >> 1;
    const int g = lane >> 2;
    const int tg = lane & 3;

    const uint32_t smb = (uint32_t)__cvta_generic_to_shared(smh);

    // ldmatrix lane->address components (canonical m8n8 tiling)
    const int a_row = lane & 15;               // row within 16-row tile
    const int a_kb  = (lane >> 4) << 3;        // 0 or 8 (k-halves)
    const int b_row = lane & 7;                // row within 8-row tile (lanes 0-15 used)
    const int b_kb  = ((lane >> 3) & 1) << 3;  // 0 or 8

    const __half* Ab = A + (size_t)bz * sA;
    const __half* Bb = B + (size_t)bz * sB;

    float acc[4][NF][4];
    #pragma unroll
    for (int i = 0; i < 4; i++)
        #pragma unroll
        for (int j = 0; j < NF; j++)
            #pragma unroll
            for (int r = 0; r < 4; r++) acc[i][j][r] = 0.f;

    auto loadStage = [&](int st, int k0) {
        __half* Ad = As + st * ASTG;
        __half* Bd = Bs + st * BSTG;
        #pragma unroll
        for (int j = 0; j < 2; j++) {            // A: 512 chunks of 16B
            int id = tid + j * 256;
            int row = id >> 2, part = id & 3;
            cpa16(Ad + row * RSTR + part * 8,
                  Ab + (size_t)(m0 + row) * lda + k0 + part * 8);
        }
        #pragma unroll
        for (int j = 0; j < NT / 64; j++) {      // B: NT*4 chunks
            int id = tid + j * 256;
            int row = id >> 2, part = id & 3;
            cpa16(Bd + row * RSTR + part * 8,
                  Bb + (size_t)(n0 + row) * ldb + k0 + part * 8);
        }
        asm volatile("cp.async.commit_group;\n");
    };

    const int T = K >> 5;
    loadStage(0, 0);

    for (int t = 0; t < T; t++) {
        if (t + 1 < T) {
            loadStage((t + 1) & 1, (t + 1) << 5);
            asm volatile("cp.async.wait_group 1;\n");
        } else {
            asm volatile("cp.async.wait_group 0;\n");
        }
        __syncthreads();

        const uint32_t Aoff = smb + (uint32_t)((t & 1) * ASTG) * 2u;
        const uint32_t Boff = smb + (uint32_t)(2 * ASTG + (t & 1) * BSTG) * 2u;
        #pragma unroll
        for (int kk = 0; kk < 32; kk += 16) {
            uint32_t a[4][4], bfr[NF][2];
            #pragma unroll
            for (int mi = 0; mi < 4; mi++)
                ldsm4(a[mi], Aoff + (uint32_t)(((wm * 64 + mi * 16 + a_row) * RSTR) + kk + a_kb) * 2u);
            #pragma unroll
            for (int ni = 0; ni < NF; ni++)
                ldsm2(bfr[ni], Boff + (uint32_t)(((wn * WNW + ni * 8 + b_row) * RSTR) + kk + b_kb) * 2u);
            #pragma unroll
            for (int mi = 0; mi < 4; mi++)
                #pragma unroll
                for (int ni = 0; ni < NF; ni++)
                    mma16(acc[mi][ni], a[mi], bfr[ni]);
        }
        __syncthreads();
    }

    // ---------------- epilogue (C pointers carry the batch offset!) ----------------
    __half* Ch = (__half*)Cv + (size_t)bz * sC;
    float*  Cf = (float*)Cv + (size_t)bz * sC;
    const float* Rb = (EPI == 2 || EPI == 4) ? (res + (size_t)bz * sRes) : nullptr;
    #pragma unroll
    for (int mi = 0; mi < 4; mi++) {
        int mr = m0 + wm * 64 + mi * 16 + g;     // rows mr, mr+8
        float bm0 = 0.f, bm8 = 0.f;
        if (EPI == 4) { bm0 = bias[mr]; bm8 = bias[mr + 8]; }
        #pragma unroll
        for (int ni = 0; ni < NF; ni++) {
            int nc = n0 + wn * WNW + ni * 8 + tg * 2;
            float v0 = acc[mi][ni][0], v1 = acc[mi][ni][1];
            float v2 = acc[mi][ni][2], v3 = acc[mi][ni][3];
            if (EPI == 1) { v0 *= alpha; v1 *= alpha; v2 *= alpha; v3 *= alpha; }
            if (EPI == 0 || EPI == 3) {
                float b0 = bias[nc], b1 = bias[nc + 1];
                v0 += b0; v1 += b1; v2 += b0; v3 += b1;
            }
            if (EPI == 3) {
                v0 = fmaxf(v0, 0.f); v1 = fmaxf(v1, 0.f);
                v2 = fmaxf(v2, 0.f); v3 = fmaxf(v3, 0.f);
            }
            if (EPI == 4) { v0 += bm0; v1 += bm0; v2 += bm8; v3 += bm8; }
            if (EPI == 2 || EPI == 4) {
                float2 r0 = *(const float2*)(Rb + (size_t)mr * ldc + nc);
                float2 r8 = *(const float2*)(Rb + (size_t)(mr + 8) * ldc + nc);
                v0 += r0.x; v1 += r0.y; v2 += r8.x; v3 += r8.y;
                *(float2*)(Cf + (size_t)mr * ldc + nc) = make_float2(v0, v1);
                *(float2*)(Cf + (size_t)(mr + 8) * ldc + nc) = make_float2(v2, v3);
            } else {
                *(__half2*)(Ch + (size_t)mr * ldc + nc) = __floats2half2_rn(v0, v1);
                *(__half2*)(Ch + (size_t)(mr + 8) * ldc + nc) = __floats2half2_rn(v2, v3);
            }
        }
    }
}

// ---------------- elementwise / prep kernels ----------------
__global__ void bn_stats_kernel(const float* __restrict__ x,
                                const float* __restrict__ gamma,
                                const float* __restrict__ beta,
                                float* __restrict__ scale,
                                float* __restrict__ shift) {
    int c = blockIdx.x;
    int tid = threadIdx.x;
    float s = 0.f, s2 = 0.f;
    const float* xc = x + (size_t)c * HW;
    for (int b = 0; b < BB; b++) {
        const float* p = xc + (size_t)b * CC * HW;
        #pragma unroll 4
        for (int i = tid; i < HW; i += 256) {
            float v = p[i];
            s += v; s2 = fmaf(v, v, s2);
        }
    }
    __shared__ float ss[256], ss2[256];
    ss[tid] = s; ss2[tid] = s2;
    __syncthreads();
    for (int o = 128; o > 0; o >>= 1) {
        if (tid < o) { ss[tid] += ss[tid + o]; ss2[tid] += ss2[tid + o]; }
        __syncthreads();
    }
    if (tid == 0) {
        const float invN = 1.0f / (BB * HW);
        float mean = ss[0] * invN;
        float var  = ss2[0] * invN - mean * mean;
        float sc = gamma[c] * rsqrtf(var + 1e-5f);
        scale[c] = sc;
        shift[c] = beta[c] - mean * sc;
    }
}

// x [c][hw] fp32 -> h^T [hw][c] half with bn1+relu
__global__ void bnT_kernel(const float* __restrict__ x, const float* __restrict__ sc,
                           const float* __restrict__ sh, __half* __restrict__ o) {
    __shared__ float t[32][33];
    int b = blockIdx.z;
    int hw0 = blockIdx.x * 32, c0 = blockIdx.y * 32;
    int tx = threadIdx.x, ty = threadIdx.y;
    const float* I = x + (size_t)b * CC * HW;
    __half* O = o + (size_t)b * HW * CC;
    #pragma unroll
    for (int j = 0; j < 32; j += 8) {
        int c = c0 + ty + j;
        float v = I[(size_t)c * HW + hw0 + tx];
        t[ty + j][tx] = fmaxf(fmaf(v, sc[c], sh[c]), 0.f);
    }
    __syncthreads();
    #pragma unroll
    for (int j = 0; j < 32; j += 8)
        O[(size_t)(hw0 + ty + j) * CC + c0 + tx] = __float2half(t[tx][ty + j]);
}

// qkt [hw][640] cols 128.. -> V [c][hw] half (batched)
__global__ void vT_kernel(const __half* __restrict__ qkt, __half* __restrict__ v) {
    __shared__ float t[32][33];
    int b = blockIdx.z;
    int hw0 = blockIdx.x * 32, c0 = blockIdx.y * 32;
    int tx = threadIdx.x, ty = threadIdx.y;
    const __half* I = qkt + (size_t)b * HW * OO;
    __half* O = v + (size_t)b * CC * HW;
    #pragma unroll
    for (int j = 0; j < 32; j += 8)
        t[ty + j][tx] = __half2float(I[(size_t)(hw0 + ty + j) * OO + 128 + c0 + tx]);
    __syncthreads();
    #pragma unroll
    for (int j = 0; j < 32; j += 8)
        O[(size_t)(c0 + ty + j) * HW + hw0 + tx] = __float2half(t[tx][ty + j]);
}

// xr fp32 [c][hw] -> xr^T half [hw][c]
__global__ void xrT_kernel(const float* __restrict__ xr, __half* __restrict__ o) {
    __shared__ float t[32][33];
    int b = blockIdx.z;
    int hw0 = blockIdx.x * 32, c0 = blockIdx.y * 32;
    int tx = threadIdx.x, ty = threadIdx.y;
    const float* I = xr + (size_t)b * CC * HW;
    __half* O = o + (size_t)b * HW * CC;
    #pragma unroll
    for (int j = 0; j < 32; j += 8)
        t[ty + j][tx] = I[(size_t)(c0 + ty + j) * HW + hw0 + tx];
    __syncthreads();
    #pragma unroll
    for (int j = 0; j < 32; j += 8)
        O[(size_t)(hw0 + ty + j) * CC + c0 + tx] = __float2half(t[tx][ty + j]);
}

__global__ void round_half(const float* __restrict__ in, __half* __restrict__ out) {
    int i = blockIdx.x * 256 + threadIdx.x;
    float4 v = ((const float4*)in)[i];
    ((__half2*)out)[i * 2]     = __floats2half2_rn(v.x, v.y);
    ((__half2*)out)[i * 2 + 1] = __floats2half2_rn(v.z, v.w);
}

__global__ void w1_fold(const float* __restrict__ W1, const float* __restrict__ b1,
                        const float* __restrict__ sc, const float* __restrict__ sh,
                        __half* __restrict__ w1f, float* __restrict__ b1f) {
    int o = blockIdx.x;
    int tid = threadIdx.x;
    float acc = 0.f;
    for (int k = tid; k < CC; k += 256) {
        float w = W1[o * CC + k];
        acc = fmaf(w, sh[k], acc);
        w1f[o * CC + k] = __float2half(w * sc[k]);
    }
    __shared__ float r[256];
    r[tid] = acc; __syncthreads();
    for (int ofs = 128; ofs > 0; ofs >>= 1) {
        if (tid < ofs) r[tid] += r[tid + ofs];
        __syncthreads();
    }
    if (tid == 0) b1f[o] = b1[o] + r[0];
}

// row softmax over contiguous 1024-half rows of S^T, in place (axis = q)
__global__ void softmax_row(__half* __restrict__ S) {
    int row = blockIdx.x * 8 + (threadIdx.x >> 5);
    int lane = threadIdx.x & 31;
    __half2* p = (__half2*)(S + (size_t)row * HW);
    float f[32];
    #pragma unroll
    for (int i = 0; i < 16; i++) {
        float2 v = __half22float2(p[i * 32 + lane]);
        f[i * 2] = v.x; f[i * 2 + 1] = v.y;
    }
    float m = -3.0e38f;
    #pragma unroll
    for (int i = 0; i < 32; i++) m = fmaxf(m, f[i]);
    #pragma unroll
    for (int o = 16; o > 0; o >>= 1) m = fmaxf(m, __shfl_xor_sync(0xffffffffu, m, o));
    float s = 0.f;
    #pragma unroll
    for (int i = 0; i < 32; i++) { f[i] = fexp(f[i] - m); s += f[i]; }
    #pragma unroll
    for (int o = 16; o > 0; o >>= 1) s += __shfl_xor_sync(0xffffffffu, s, o);
    float inv = 1.0f / s;
    #pragma unroll
    for (int i = 0; i < 16; i++)
        p[i * 32 + lane] = __floats2half2_rn(f[i * 2] * inv, f[i * 2 + 1] * inv);
}

// ---------------- launcher ----------------
extern "C" void kernel_launch(void* const* d_in, const int* in_sizes, int n_in,
                              void* d_out, int out_size) {
    const float* x     = (const float*)d_in[0];
    const float* bn1_g = (const float*)d_in[1];
    const float* bn1_b = (const float*)d_in[2];
    const float* W_qkv = (const float*)d_in[3];
    const float* b_qkv = (const float*)d_in[4];
    const float* bn2_g = (const float*)d_in[5];
    const float* bn2_b = (const float*)d_in[6];
    const float* W1    = (const float*)d_in[7];
    const float* b1    = (const float*)d_in[8];
    const float* W2    = (const float*)d_in[9];
    const float* b2    = (const float*)d_in[10];
    float* out = (float*)d_out;

    __half *p_ht, *p_qkt, *p_v, *p_st, *p_xrt, *p_zt, *p_wqh, *p_w1f, *p_w2h;
    float *p_xr, *p_b1f, *p_s1, *p_h1, *p_s2, *p_h2;
    cudaGetSymbolAddress((void**)&p_ht,  g_ht);
    cudaGetSymbolAddress((void**)&p_qkt, g_qkt);
    cudaGetSymbolAddress((void**)&p_v,   g_v);
    cudaGetSymbolAddress((void**)&p_st,  g_st);
    cudaGetSymbolAddress((void**)&p_xr,  g_xr);
    cudaGetSymbolAddress((void**)&p_xrt, g_xrt);
    cudaGetSymbolAddress((void**)&p_zt,  g_zt);
    cudaGetSymbolAddress((void**)&p_wqh, g_wqh);
    cudaGetSymbolAddress((void**)&p_w1f, g_w1f);
    cudaGetSymbolAddress((void**)&p_w2h, g_w2h);
    cudaGetSymbolAddress((void**)&p_b1f, g_b1f);
    cudaGetSymbolAddress((void**)&p_s1,  g_s1);
    cudaGetSymbolAddress((void**)&p_h1,  g_h1);
    cudaGetSymbolAddress((void**)&p_s2,  g_s2);
    cudaGetSymbolAddress((void**)&p_h2,  g_h2);

    const int SM128 = (2 * ASTG + 2 * 128 * RSTR) * 2;
    const int SM256 = (2 * ASTG + 2 * 256 * RSTR) * 2;
    cudaFuncSetAttribute(hgemm<128, 0>, cudaFuncAttributeMaxDynamicSharedMemorySize, SM128);
    cudaFuncSetAttribute(hgemm<256, 1>, cudaFuncAttributeMaxDynamicSharedMemorySize, SM256);
    cudaFuncSetAttribute(hgemm<256, 2>, cudaFuncAttributeMaxDynamicSharedMemorySize, SM256);
    cudaFuncSetAttribute(hgemm<256, 3>, cudaFuncAttributeMaxDynamicSharedMemorySize, SM256);
    cudaFuncSetAttribute(hgemm<256, 4>, cudaFuncAttributeMaxDynamicSharedMemorySize, SM256);

    const long sX  = (long)CC * HW;
    const long sHT = (long)HW * CC;
    const long sQK = (long)HW * OO;
    const long sS  = (long)HW * HW;

    // prep: weights to half (W_qkv, W2), bn1 stats, h^T
    round_half<<<OO * CC / 1024, 256>>>(W_qkv, p_wqh);
    round_half<<<CC * CC / 1024, 256>>>(W2, p_w2h);
    bn_stats_kernel<<<CC, 256>>>(x, bn1_g, bn1_b, p_s1, p_h1);
    bnT_kernel<<<dim3(HW / 32, CC / 32, BB), dim3(32, 8)>>>(x, p_s1, p_h1, p_ht);

    // qkt[hw][o] = h^T . W_qkv^T + b_qkv   (A=h^T, B=W_qkv)
    hgemm<128, 0><<<dim3(5, 8, BB), 256, SM128>>>(
        p_ht, p_wqh, p_qkt, CC, CC, CC, OO,
        sHT, 0L, sQK, b_qkv, nullptr, 0L, 1.0f);

    // S^T[k'][q] = (K . Q^T)/8   (A=qkt+64, B=qkt)
    hgemm<256, 1><<<dim3(4, 8, BB), 256, SM256>>>(
        p_qkt + 64, p_qkt, p_st, DD, OO, OO, HW,
        sQK, sQK, sS, nullptr, nullptr, 0L, 0.125f);

    // P^T row softmax in place
    softmax_row<<<BB * HW / 8, 256>>>(p_st);

    // V [c][hw] from qkt cols 128..639
    vT_kernel<<<dim3(HW / 32, CC / 32, BB), dim3(32, 8)>>>(p_qkt, p_v);

    // xr = x + V . P    (A=V [c][q], B=P^T [k'][q])
    hgemm<256, 2><<<dim3(4, 4, BB), 256, SM256>>>(
        p_v, p_st, p_xr, HW, HW, HW, HW,
        sX, sS, sX, nullptr, x, sX, 1.0f);

    // xr^T half
    xrT_kernel<<<dim3(HW / 32, CC / 32, BB), dim3(32, 8)>>>(p_xr, p_xrt);

    // bn2 stats + fold into W1
    bn_stats_kernel<<<CC, 256>>>(p_xr, bn2_g, bn2_b, p_s2, p_h2);
    w1_fold<<<CC, 256>>>(W1, b1, p_s2, p_h2, p_w1f, p_b1f);

    // z^T[hw][o] = relu(xr^T . W1'^T + b1')   (A=xr^T, B=w1f)
    hgemm<256, 3><<<dim3(2, 8, BB), 256, SM256>>>(
        p_xrt, p_w1f, p_zt, CC, CC, CC, CC,
        sHT, 0L, sHT, p_b1f, nullptr, 0L, 1.0f);

    // out[c][hw] = xr + W2 . z + b2   (A=W2 [c][o], B=z^T [hw][o])
    hgemm<256, 4><<<dim3(4, 4, BB), 256, SM256>>>(
        p_w2h, p_zt, out, CC, CC, CC, HW,
        0L, sHT, sX, b2, p_xr, sX, 1.0f);
}

// round 9
// speedup vs baseline: 1.7370x; 1.0450x over previous
#include <cuda_runtime.h>
#include <cuda_fp16.h>
#include <math.h>
#include <stdint.h>

#define BB 32
#define CC 512
#define HW 1024
#define DD 64
#define OO 640

// ---------------- scratch (device globals) ----------------
__device__ __half g_ht[(size_t)BB * HW * CC];    // h1^T [b][hw][c]
__device__ __half g_qkt[(size_t)BB * HW * 128];  // [b][hw][0:64=q,64:128=k]
__device__ __half g_v[(size_t)BB * CC * HW];     // V [b][c][hw]
__device__ __half g_st[(size_t)BB * HW * HW];    // S^T then P^T [b][k'][q]
__device__ float  g_xr[(size_t)BB * CC * HW];    // xr fp32 [b][c][hw]
__device__ __half g_xrt[(size_t)BB * HW * CC];   // xr^T half [b][hw][c]
__device__ __half g_zt[(size_t)BB * HW * CC];    // z^T [b][hw][o]
__device__ __half g_wqh[OO * CC];                // W_qkv half [o][c]
__device__ __half g_w1f[CC * CC];                // (W1*bn2sc) half [o][c]
__device__ __half g_w2h[CC * CC];                // W2 half [c][o]
__device__ float  g_b1f[CC];
__device__ float  g_s1[CC], g_h1[CC], g_s2[CC], g_h2[CC];

// ---------------- helpers ----------------
__device__ __forceinline__ float fexp(float x) {
    x = fmaxf(x, -87.0f);
    float t  = x * 1.4426950408889634f;
    float fi = floorf(t);
    float f  = t - fi;
    float r = 1.5403530e-4f;
    r = fmaf(r, f, 1.3333558e-3f);
    r = fmaf(r, f, 9.6181291e-3f);
    r = fmaf(r, f, 5.5504109e-2f);
    r = fmaf(r, f, 2.4022651e-1f);
    r = fmaf(r, f, 6.9314718e-1f);
    r = fmaf(r, f, 1.0f);
    return r * __int_as_float(((int)fi + 127) << 23);
}
__device__ __forceinline__ void cpa16(void* s, const void* g) {
    unsigned ss = (unsigned)__cvta_generic_to_shared(s);
    asm volatile("cp.async.cg.shared.global [%0], [%1], 16;\n" :: "r"(ss), "l"(g));
}
__device__ __forceinline__ void mma16(float* c, const uint32_t* a, const uint32_t* b) {
    asm volatile(
        "mma.sync.aligned.m16n8k16.row.col.f32.f16.f16.f32 "
        "{%0,%1,%2,%3}, {%4,%5,%6,%7}, {%8,%9}, {%0,%1,%2,%3};\n"
        : "+f"(c[0]), "+f"(c[1]), "+f"(c[2]), "+f"(c[3])
        : "r"(a[0]), "r"(a[1]), "r"(a[2]), "r"(a[3]), "r"(b[0]), "r"(b[1]));
}
__device__ __forceinline__ void ldsm4(uint32_t* r, uint32_t addr) {
    asm volatile("ldmatrix.sync.aligned.m8n8.x4.shared.b16 {%0,%1,%2,%3}, [%4];"
        : "=r"(r[0]), "=r"(r[1]), "=r"(r[2]), "=r"(r[3]) : "r"(addr));
}
__device__ __forceinline__ void ldsm2(uint32_t* r, uint32_t addr) {
    asm volatile("ldmatrix.sync.aligned.m8n8.x2.shared.b16 {%0,%1}, [%2];"
        : "=r"(r[0]), "=r"(r[1]) : "r"(addr));
}

// ---------------- fp16 tensor GEMM ----------------
// C[m,n] = alpha * sum_k A[m][k] * B[n][k]  (A row-major, B n-major, both k-contig half)
// CTA: 128(M) x NT(N), 8 warps, k-stage 32, 3-stage cp.async ring, one sync/iter.
// EPI: 0 = half store + bias[n]
//      1 = half store * alpha
//      2 = fp32 store + res
//      3 = half store + bias[n] + relu
//      4 = fp32 store + bias[m] + res
//      5 = half store + bias[m]
#define RSTR 40                    // 32 + 8 halves pad (80B row, conflict-free ldmatrix)
#define ASTG (128 * RSTR)

template <int NT, int EPI>
__global__ void __launch_bounds__(256, 1) hgemm(
    const __half* __restrict__ A, const __half* __restrict__ B, void* __restrict__ Cv,
    int K, int lda, int ldb, int ldc,
    long sA, long sB, long sC,
    const float* __restrict__ bias,
    const float* __restrict__ res, long sRes,
    float alpha)
{
    constexpr int BSTG = NT * RSTR;
    constexpr int NF = (NT == 256) ? 8 : 4;   // n-frags per warp
    constexpr int WNW = (NT == 256) ? 64 : 32;

    extern __shared__ __align__(16) __half smh[];
    __half* As = smh;                  // 3 stages
    __half* Bs = smh + 3 * ASTG;

    const int bz = blockIdx.z;
    const int n0 = blockIdx.x * NT;
    const int m0 = blockIdx.y * 128;
    const int tid = threadIdx.x;
    const int warp = tid >> 5;
    const int lane = tid & 31;
    const int wm = warp & 1;
    const int wn = warp >> 1;
    const int g = lane >> 2;
    const int tg = lane & 3;

    const uint32_t smb = (uint32_t)__cvta_generic_to_shared(smh);

    const int a_row = lane & 15;
    const int a_kb  = (lane >> 4) << 3;
    const int b_row = lane & 7;
    const int b_kb  = ((lane >> 3) & 1) << 3;

    const __half* Ab = A + (size_t)bz * sA;
    const __half* Bb = B + (size_t)bz * sB;

    float acc[4][NF][4];
    #pragma unroll
    for (int i = 0; i < 4; i++)
        #pragma unroll
        for (int j = 0; j < NF; j++)
            #pragma unroll
            for (int r = 0; r < 4; r++) acc[i][j][r] = 0.f;

    auto loadStage = [&](int st, int k0) {
        __half* Ad = As + st * ASTG;
        __half* Bd = Bs + st * BSTG;
        #pragma unroll
        for (int j = 0; j < 2; j++) {            // A: 512 chunks of 16B
            int id = tid + j * 256;
            int row = id >> 2, part = id & 3;
            cpa16(Ad + row * RSTR + part * 8,
                  Ab + (size_t)(m0 + row) * lda + k0 + part * 8);
        }
        #pragma unroll
        for (int j = 0; j < NT / 64; j++) {      // B: NT*4 chunks
            int id = tid + j * 256;
            int row = id >> 2, part = id & 3;
            cpa16(Bd + row * RSTR + part * 8,
                  Bb + (size_t)(n0 + row) * ldb + k0 + part * 8);
        }
        asm volatile("cp.async.commit_group;\n");
    };

    const int T = K >> 5;
    loadStage(0, 0);
    if (T > 1) loadStage(1, 32);

    for (int t = 0; t < T; t++) {
        if (t + 1 < T) asm volatile("cp.async.wait_group 1;\n");
        else           asm volatile("cp.async.wait_group 0;\n");
        __syncthreads();
        if (t + 2 < T) loadStage((t + 2) % 3, (t + 2) << 5);

        const int st = t % 3;
        const uint32_t Aoff = smb + (uint32_t)(st * ASTG) * 2u;
        const uint32_t Boff = smb + (uint32_t)(3 * ASTG + st * BSTG) * 2u;
        #pragma unroll
        for (int kk = 0; kk < 32; kk += 16) {
            uint32_t a[4][4], bfr[NF][2];
            #pragma unroll
            for (int mi = 0; mi < 4; mi++)
                ldsm4(a[mi], Aoff + (uint32_t)(((wm * 64 + mi * 16 + a_row) * RSTR) + kk + a_kb) * 2u);
            #pragma unroll
            for (int ni = 0; ni < NF; ni++)
                ldsm2(bfr[ni], Boff + (uint32_t)(((wn * WNW + ni * 8 + b_row) * RSTR) + kk + b_kb) * 2u);
            #pragma unroll
            for (int mi = 0; mi < 4; mi++)
                #pragma unroll
                for (int ni = 0; ni < NF; ni++)
                    mma16(acc[mi][ni], a[mi], bfr[ni]);
        }
    }

    // ---------------- epilogue ----------------
    __half* Ch = (__half*)Cv + (size_t)bz * sC;
    float*  Cf = (float*)Cv + (size_t)bz * sC;
    const float* Rb = (EPI == 2 || EPI == 4) ? (res + (size_t)bz * sRes) : nullptr;
    #pragma unroll
    for (int mi = 0; mi < 4; mi++) {
        int mr = m0 + wm * 64 + mi * 16 + g;     // rows mr, mr+8
        float bm0 = 0.f, bm8 = 0.f;
        if (EPI == 4 || EPI == 5) { bm0 = bias[mr]; bm8 = bias[mr + 8]; }
        #pragma unroll
        for (int ni = 0; ni < NF; ni++) {
            int nc = n0 + wn * WNW + ni * 8 + tg * 2;
            float v0 = acc[mi][ni][0], v1 = acc[mi][ni][1];
            float v2 = acc[mi][ni][2], v3 = acc[mi][ni][3];
            if (EPI == 1) { v0 *= alpha; v1 *= alpha; v2 *= alpha; v3 *= alpha; }
            if (EPI == 0 || EPI == 3) {
                float b0 = bias[nc], b1 = bias[nc + 1];
                v0 += b0; v1 += b1; v2 += b0; v3 += b1;
            }
            if (EPI == 3) {
                v0 = fmaxf(v0, 0.f); v1 = fmaxf(v1, 0.f);
                v2 = fmaxf(v2, 0.f); v3 = fmaxf(v3, 0.f);
            }
            if (EPI == 4 || EPI == 5) { v0 += bm0; v1 += bm0; v2 += bm8; v3 += bm8; }
            if (EPI == 2 || EPI == 4) {
                float2 r0 = *(const float2*)(Rb + (size_t)mr * ldc + nc);
                float2 r8 = *(const float2*)(Rb + (size_t)(mr + 8) * ldc + nc);
                v0 += r0.x; v1 += r0.y; v2 += r8.x; v3 += r8.y;
                *(float2*)(Cf + (size_t)mr * ldc + nc) = make_float2(v0, v1);
                *(float2*)(Cf + (size_t)(mr + 8) * ldc + nc) = make_float2(v2, v3);
            } else {
                *(__half2*)(Ch + (size_t)mr * ldc + nc) = __floats2half2_rn(v0, v1);
                *(__half2*)(Ch + (size_t)(mr + 8) * ldc + nc) = __floats2half2_rn(v2, v3);
            }
        }
    }
}

// ---------------- elementwise / prep kernels ----------------
__global__ void bn_stats_kernel(const float* __restrict__ x,
                                const float* __restrict__ gamma,
                                const float* __restrict__ beta,
                                float* __restrict__ scale,
                                float* __restrict__ shift) {
    int c = blockIdx.x;
    int tid = threadIdx.x;
    float s = 0.f, s2 = 0.f;
    const float* xc = x + (size_t)c * HW;
    for (int b = 0; b < BB; b++) {
        const float* p = xc + (size_t)b * CC * HW;
        #pragma unroll 4
        for (int i = tid; i < HW; i += 256) {
            float v = p[i];
            s += v; s2 = fmaf(v, v, s2);
        }
    }
    __shared__ float ss[256], ss2[256];
    ss[tid] = s; ss2[tid] = s2;
    __syncthreads();
    for (int o = 128; o > 0; o >>= 1) {
        if (tid < o) { ss[tid] += ss[tid + o]; ss2[tid] += ss2[tid + o]; }
        __syncthreads();
    }
    if (tid == 0) {
        const float invN = 1.0f / (BB * HW);
        float mean = ss[0] * invN;
        float var  = ss2[0] * invN - mean * mean;
        float sc = gamma[c] * rsqrtf(var + 1e-5f);
        scale[c] = sc;
        shift[c] = beta[c] - mean * sc;
    }
}

// x [c][hw] fp32 -> h^T [hw][c] half with bn1+relu
__global__ void bnT_kernel(const float* __restrict__ x, const float* __restrict__ sc,
                           const float* __restrict__ sh, __half* __restrict__ o) {
    __shared__ float t[32][33];
    int b = blockIdx.z;
    int hw0 = blockIdx.x * 32, c0 = blockIdx.y * 32;
    int tx = threadIdx.x, ty = threadIdx.y;
    const float* I = x + (size_t)b * CC * HW;
    __half* O = o + (size_t)b * HW * CC;
    #pragma unroll
    for (int j = 0; j < 32; j += 8) {
        int c = c0 + ty + j;
        float v = I[(size_t)c * HW + hw0 + tx];
        t[ty + j][tx] = fmaxf(fmaf(v, sc[c], sh[c]), 0.f);
    }
    __syncthreads();
    #pragma unroll
    for (int j = 0; j < 32; j += 8)
        O[(size_t)(hw0 + ty + j) * CC + c0 + tx] = __float2half(t[tx][ty + j]);
}

// xr fp32 [c][hw] -> xr^T half [hw][c]
__global__ void xrT_kernel(const float* __restrict__ xr, __half* __restrict__ o) {
    __shared__ float t[32][33];
    int b = blockIdx.z;
    int hw0 = blockIdx.x * 32, c0 = blockIdx.y * 32;
    int tx = threadIdx.x, ty = threadIdx.y;
    const float* I = xr + (size_t)b * CC * HW;
    __half* O = o + (size_t)b * HW * CC;
    #pragma unroll
    for (int j = 0; j < 32; j += 8)
        t[ty + j][tx] = I[(size_t)(c0 + ty + j) * HW + hw0 + tx];
    __syncthreads();
    #pragma unroll
    for (int j = 0; j < 32; j += 8)
        O[(size_t)(hw0 + ty + j) * CC + c0 + tx] = __float2half(t[tx][ty + j]);
}

__global__ void round_half(const float* __restrict__ in, __half* __restrict__ out) {
    int i = blockIdx.x * 256 + threadIdx.x;
    float4 v = ((const float4*)in)[i];
    ((__half2*)out)[i * 2]     = __floats2half2_rn(v.x, v.y);
    ((__half2*)out)[i * 2 + 1] = __floats2half2_rn(v.z, v.w);
}

__global__ void w1_fold(const float* __restrict__ W1, const float* __restrict__ b1,
                        const float* __restrict__ sc, const float* __restrict__ sh,
                        __half* __restrict__ w1f, float* __restrict__ b1f) {
    int o = blockIdx.x;
    int tid = threadIdx.x;
    float acc = 0.f;
    for (int k = tid; k < CC; k += 256) {
        float w = W1[o * CC + k];
        acc = fmaf(w, sh[k], acc);
        w1f[o * CC + k] = __float2half(w * sc[k]);
    }
    __shared__ float r[256];
    r[tid] = acc; __syncthreads();
    for (int ofs = 128; ofs > 0; ofs >>= 1) {
        if (tid < ofs) r[tid] += r[tid + ofs];
        __syncthreads();
    }
    if (tid == 0) b1f[o] = b1[o] + r[0];
}

// row softmax over contiguous 1024-half rows of S^T, in place (axis = q)
__global__ void softmax_row(__half* __restrict__ S) {
    int row = blockIdx.x * 8 + (threadIdx.x >> 5);
    int lane = threadIdx.x & 31;
    __half2* p = (__half2*)(S + (size_t)row * HW);
    float f[32];
    #pragma unroll
    for (int i = 0; i < 16; i++) {
        float2 v = __half22float2(p[i * 32 + lane]);
        f[i * 2] = v.x; f[i * 2 + 1] = v.y;
    }
    float m = -3.0e38f;
    #pragma unroll
    for (int i = 0; i < 32; i++) m = fmaxf(m, f[i]);
    #pragma unroll
    for (int o = 16; o > 0; o >>= 1) m = fmaxf(m, __shfl_xor_sync(0xffffffffu, m, o));
    float s = 0.f;
    #pragma unroll
    for (int i = 0; i < 32; i++) { f[i] = fexp(f[i] - m); s += f[i]; }
    #pragma unroll
    for (int o = 16; o > 0; o >>= 1) s += __shfl_xor_sync(0xffffffffu, s, o);
    float inv = 1.0f / s;
    #pragma unroll
    for (int i = 0; i < 16; i++)
        p[i * 32 + lane] = __floats2half2_rn(f[i * 2] * inv, f[i * 2 + 1] * inv);
}

// ---------------- launcher ----------------
extern "C" void kernel_launch(void* const* d_in, const int* in_sizes, int n_in,
                              void* d_out, int out_size) {
    const float* x     = (const float*)d_in[0];
    const float* bn1_g = (const float*)d_in[1];
    const float* bn1_b = (const float*)d_in[2];
    const float* W_qkv = (const float*)d_in[3];
    const float* b_qkv = (const float*)d_in[4];
    const float* bn2_g = (const float*)d_in[5];
    const float* bn2_b = (const float*)d_in[6];
    const float* W1    = (const float*)d_in[7];
    const float* b1    = (const float*)d_in[8];
    const float* W2    = (const float*)d_in[9];
    const float* b2    = (const float*)d_in[10];
    float* out = (float*)d_out;

    __half *p_ht, *p_qkt, *p_v, *p_st, *p_xrt, *p_zt, *p_wqh, *p_w1f, *p_w2h;
    float *p_xr, *p_b1f, *p_s1, *p_h1, *p_s2, *p_h2;
    cudaGetSymbolAddress((void**)&p_ht,  g_ht);
    cudaGetSymbolAddress((void**)&p_qkt, g_qkt);
    cudaGetSymbolAddress((void**)&p_v,   g_v);
    cudaGetSymbolAddress((void**)&p_st,  g_st);
    cudaGetSymbolAddress((void**)&p_xr,  g_xr);
    cudaGetSymbolAddress((void**)&p_xrt, g_xrt);
    cudaGetSymbolAddress((void**)&p_zt,  g_zt);
    cudaGetSymbolAddress((void**)&p_wqh, g_wqh);
    cudaGetSymbolAddress((void**)&p_w1f, g_w1f);
    cudaGetSymbolAddress((void**)&p_w2h, g_w2h);
    cudaGetSymbolAddress((void**)&p_b1f, g_b1f);
    cudaGetSymbolAddress((void**)&p_s1,  g_s1);
    cudaGetSymbolAddress((void**)&p_h1,  g_h1);
    cudaGetSymbolAddress((void**)&p_s2,  g_s2);
    cudaGetSymbolAddress((void**)&p_h2,  g_h2);

    const int SM128 = (3 * ASTG + 3 * 128 * RSTR) * 2;
    const int SM256 = (3 * ASTG + 3 * 256 * RSTR) * 2;
    cudaFuncSetAttribute(hgemm<128, 0>, cudaFuncAttributeMaxDynamicSharedMemorySize, SM128);
    cudaFuncSetAttribute(hgemm<256, 5>, cudaFuncAttributeMaxDynamicSharedMemorySize, SM256);
    cudaFuncSetAttribute(hgemm<256, 1>, cudaFuncAttributeMaxDynamicSharedMemorySize, SM256);
    cudaFuncSetAttribute(hgemm<256, 2>, cudaFuncAttributeMaxDynamicSharedMemorySize, SM256);
    cudaFuncSetAttribute(hgemm<256, 3>, cudaFuncAttributeMaxDynamicSharedMemorySize, SM256);
    cudaFuncSetAttribute(hgemm<256, 4>, cudaFuncAttributeMaxDynamicSharedMemorySize, SM256);

    const long sX  = (long)CC * HW;
    const long sHT = (long)HW * CC;
    const long sQK = (long)HW * 128;
    const long sS  = (long)HW * HW;

    // prep: weights to half (W_qkv, W2), bn1 stats, h^T
    round_half<<<OO * CC / 1024, 256>>>(W_qkv, p_wqh);
    round_half<<<CC * CC / 1024, 256>>>(W2, p_w2h);
    bn_stats_kernel<<<CC, 256>>>(x, bn1_g, bn1_b, p_s1, p_h1);
    bnT_kernel<<<dim3(HW / 32, CC / 32, BB), dim3(32, 8)>>>(x, p_s1, p_h1, p_ht);

    // qk[hw][128] = h^T . Wqk^T + b_qkv[0:128]   (A=h^T, B=wqh rows 0..127)
    hgemm<128, 0><<<dim3(1, 8, BB), 256, SM128>>>(
        p_ht, p_wqh, p_qkt, CC, CC, CC, 128,
        sHT, 0L, sQK, b_qkv, nullptr, 0L, 1.0f);

    // V[c][hw] = Wv . h + b_qkv[128+c]   (A=wqh rows 128.., B=h^T)
    hgemm<256, 5><<<dim3(4, 4, BB), 256, SM256>>>(
        p_wqh + 128 * CC, p_ht, p_v, CC, CC, CC, HW,
        0L, sHT, sX, b_qkv + 128, nullptr, 0L, 1.0f);

    // S^T[k'][q] = (K . Q^T)/8   (A=qkt+64, B=qkt)
    hgemm<256, 1><<<dim3(4, 8, BB), 256, SM256>>>(
        p_qkt + 64, p_qkt, p_st, DD, 128, 128, HW,
        sQK, sQK, sS, nullptr, nullptr, 0L, 0.125f);

    // P^T row softmax in place
    softmax_row<<<BB * HW / 8, 256>>>(p_st);

    // xr = x + V . P    (A=V [c][q], B=P^T [k'][q])
    hgemm<256, 2><<<dim3(4, 4, BB), 256, SM256>>>(
        p_v, p_st, p_xr, HW, HW, HW, HW,
        sX, sS, sX, nullptr, x, sX, 1.0f);

    // xr^T half
    xrT_kernel<<<dim3(HW / 32, CC / 32, BB), dim3(32, 8)>>>(p_xr, p_xrt);

    // bn2 stats + fold into W1
    bn_stats_kernel<<<CC, 256>>>(p_xr, bn2_g, bn2_b, p_s2, p_h2);
    w1_fold<<<CC, 256>>>(W1, b1, p_s2, p_h2, p_w1f, p_b1f);

    // z^T[hw][o] = relu(xr^T . W1'^T + b1')   (A=xr^T, B=w1f)
    hgemm<256, 3><<<dim3(2, 8, BB), 256, SM256>>>(
        p_xrt, p_w1f, p_zt, CC, CC, CC, CC,
        sHT, 0L, sHT, p_b1f, nullptr, 0L, 1.0f);

    // out[c][hw] = xr + W2 . z + b2   (A=W2 [c][o], B=z^T [hw][o])
    hgemm<256, 4><<<dim3(4, 4, BB), 256, SM256>>>(
        p_w2h, p_zt, out, CC, CC, CC, HW,
        0L, sHT, sX, b2, p_xr, sX, 1.0f);
}

// round 10
// speedup vs baseline: 2.1109x; 1.2152x over previous
#include <cuda_runtime.h>
#include <cuda_fp16.h>
#include <math.h>
#include <stdint.h>

#define BB 32
#define CC 512
#define HW 1024
#define DD 64
#define OO 640

// ---------------- scratch (device globals) ----------------
__device__ __half g_ht[(size_t)BB * HW * CC];    // h1^T [b][hw][c]
__device__ __half g_qkt[(size_t)BB * HW * 128];  // [b][hw][0:64=q,64:128=k]
__device__ __half g_v[(size_t)BB * CC * HW];     // V [b][c][hw]
__device__ __half g_st[(size_t)BB * HW * HW];    // S^T then P^T [b][k'][q]
__device__ float  g_xr[(size_t)BB * CC * HW];    // xr fp32 [b][c][hw]
__device__ __half g_xrt[(size_t)BB * HW * CC];   // xr^T half [b][hw][c]
__device__ __half g_zt[(size_t)BB * HW * CC];    // z^T [b][hw][o]
__device__ __half g_wqh[OO * CC];                // W_qkv half [o][c]
__device__ __half g_w1f[CC * CC];                // (W1*bn2sc) half [o][c]
__device__ __half g_w2h[CC * CC];                // W2 half [c][o]
__device__ float  g_b1f[CC];
__device__ float  g_s1[CC], g_h1[CC], g_s2[CC], g_h2[CC];
__device__ float  g_psum[256 * CC];              // bn2 partials [slot][c]
__device__ float  g_psum2[256 * CC];

// ---------------- helpers ----------------
__device__ __forceinline__ float fexp(float x) {
    x = fmaxf(x, -87.0f);
    float t  = x * 1.4426950408889634f;
    float fi = floorf(t);
    float f  = t - fi;
    float r = 1.5403530e-4f;
    r = fmaf(r, f, 1.3333558e-3f);
    r = fmaf(r, f, 9.6181291e-3f);
    r = fmaf(r, f, 5.5504109e-2f);
    r = fmaf(r, f, 2.4022651e-1f);
    r = fmaf(r, f, 6.9314718e-1f);
    r = fmaf(r, f, 1.0f);
    return r * __int_as_float(((int)fi + 127) << 23);
}
__device__ __forceinline__ void cpa16(void* s, const void* g) {
    unsigned ss = (unsigned)__cvta_generic_to_shared(s);
    asm volatile("cp.async.cg.shared.global [%0], [%1], 16;\n" :: "r"(ss), "l"(g));
}
__device__ __forceinline__ void mma16(float* c, const uint32_t* a, const uint32_t* b) {
    asm volatile(
        "mma.sync.aligned.m16n8k16.row.col.f32.f16.f16.f32 "
        "{%0,%1,%2,%3}, {%4,%5,%6,%7}, {%8,%9}, {%0,%1,%2,%3};\n"
        : "+f"(c[0]), "+f"(c[1]), "+f"(c[2]), "+f"(c[3])
        : "r"(a[0]), "r"(a[1]), "r"(a[2]), "r"(a[3]), "r"(b[0]), "r"(b[1]));
}
__device__ __forceinline__ void ldsm4(uint32_t* r, uint32_t addr) {
    asm volatile("ldmatrix.sync.aligned.m8n8.x4.shared.b16 {%0,%1,%2,%3}, [%4];"
        : "=r"(r[0]), "=r"(r[1]), "=r"(r[2]), "=r"(r[3]) : "r"(addr));
}
__device__ __forceinline__ void ldsm2(uint32_t* r, uint32_t addr) {
    asm volatile("ldmatrix.sync.aligned.m8n8.x2.shared.b16 {%0,%1}, [%2];"
        : "=r"(r[0]), "=r"(r[1]) : "r"(addr));
}

// ---------------- fp16 tensor GEMM ----------------
// C[m,n] = alpha * sum_k A[m][k] * B[n][k]; CTA 128x128, 8 warps (2m x 4n),
// k-stage 32, 3-stage cp.async ring, occupancy 2.
// EPI: 0 = half store + bias[n]
//      1 = half store * alpha
//      3 = half store + bias[n] + relu
//      4 = fp32 store + bias[m] + res
//      5 = half store + bias[m]
//      6 = fp32 store + res, plus: xrt (half, transposed) + bn2 partial sums
#define RSTR 40                    // 32 + 8 halves pad
#define ASTG (128 * RSTR)
#define SMB  (3 * 2 * ASTG * 2)    // 61440 bytes

template <int EPI>
__global__ void __launch_bounds__(256, 2) hgemm(
    const __half* __restrict__ A, const __half* __restrict__ B, void* __restrict__ Cv,
    int K, int lda, int ldb, int ldc,
    long sA, long sB, long sC,
    const float* __restrict__ bias,
    const float* __restrict__ res, long sRes,
    __half* __restrict__ aux, long sAux,
    float* __restrict__ ps, float* __restrict__ ps2,
    float alpha)
{
    extern __shared__ __align__(16) __half smh[];
    __half* As = smh;                  // 3 stages A
    __half* Bs = smh + 3 * ASTG;       // 3 stages B

    const int bz = blockIdx.z;
    const int n0 = blockIdx.x * 128;
    const int m0 = blockIdx.y * 128;
    const int tid = threadIdx.x;
    const int warp = tid >> 5;
    const int lane = tid & 31;
    const int wm = warp & 1;
    const int wn = warp >> 1;
    const int g = lane >> 2;
    const int tg = lane & 3;

    const uint32_t smb = (uint32_t)__cvta_generic_to_shared(smh);

    const int a_row = lane & 15;
    const int a_kb  = (lane >> 4) << 3;
    const int b_row = lane & 7;
    const int b_kb  = ((lane >> 3) & 1) << 3;

    const __half* Ab = A + (size_t)bz * sA;
    const __half* Bb = B + (size_t)bz * sB;

    float acc[4][4][4];
    #pragma unroll
    for (int i = 0; i < 4; i++)
        #pragma unroll
        for (int j = 0; j < 4; j++)
            #pragma unroll
            for (int r = 0; r < 4; r++) acc[i][j][r] = 0.f;

    auto loadStage = [&](int st, int k0) {
        __half* Ad = As + st * ASTG;
        __half* Bd = Bs + st * ASTG;
        #pragma unroll
        for (int j = 0; j < 2; j++) {
            int id = tid + j * 256;
            int row = id >> 2, part = id & 3;
            cpa16(Ad + row * RSTR + part * 8,
                  Ab + (size_t)(m0 + row) * lda + k0 + part * 8);
            cpa16(Bd + row * RSTR + part * 8,
                  Bb + (size_t)(n0 + row) * ldb + k0 + part * 8);
        }
        asm volatile("cp.async.commit_group;\n");
    };

    const int T = K >> 5;
    loadStage(0, 0);
    if (T > 1) loadStage(1, 32);

    for (int t = 0; t < T; t++) {
        if (t + 1 < T) asm volatile("cp.async.wait_group 1;\n");
        else           asm volatile("cp.async.wait_group 0;\n");
        __syncthreads();
        if (t + 2 < T) loadStage((t + 2) % 3, (t + 2) << 5);

        const int st = t % 3;
        const uint32_t Aoff = smb + (uint32_t)(st * ASTG) * 2u;
        const uint32_t Boff = smb + (uint32_t)((3 + st) * ASTG) * 2u;
        #pragma unroll
        for (int kk = 0; kk < 32; kk += 16) {
            uint32_t a[4][4], bfr[4][2];
            #pragma unroll
            for (int mi = 0; mi < 4; mi++)
                ldsm4(a[mi], Aoff + (uint32_t)(((wm * 64 + mi * 16 + a_row) * RSTR) + kk + a_kb) * 2u);
            #pragma unroll
            for (int ni = 0; ni < 4; ni++)
                ldsm2(bfr[ni], Boff + (uint32_t)(((wn * 32 + ni * 8 + b_row) * RSTR) + kk + b_kb) * 2u);
            #pragma unroll
            for (int mi = 0; mi < 4; mi++)
                #pragma unroll
                for (int ni = 0; ni < 4; ni++)
                    mma16(acc[mi][ni], a[mi], bfr[ni]);
        }
    }

    // ---------------- epilogue ----------------
    __half* Ch = (__half*)Cv + (size_t)bz * sC;
    float*  Cf = (float*)Cv + (size_t)bz * sC;
    const float* Rb = (EPI == 4 || EPI == 6) ? (res + (size_t)bz * sRes) : nullptr;

    if (EPI == 6) __syncthreads();   // stage smem will be reused below
    __half* smT = smh;               // [128][136] half (EPI 6)
    float*  pS  = (float*)(smh + 128 * 136);
    float*  pS2 = pS + 512;

    #pragma unroll
    for (int mi = 0; mi < 4; mi++) {
        int mr = m0 + wm * 64 + mi * 16 + g;
        float bm0 = 0.f, bm8 = 0.f;
        if (EPI == 4 || EPI == 5) { bm0 = bias[mr]; bm8 = bias[mr + 8]; }
        float rs0 = 0.f, rq0 = 0.f, rs8 = 0.f, rq8 = 0.f;
        #pragma unroll
        for (int ni = 0; ni < 4; ni++) {
            int nc = n0 + wn * 32 + ni * 8 + tg * 2;
            float v0 = acc[mi][ni][0], v1 = acc[mi][ni][1];
            float v2 = acc[mi][ni][2], v3 = acc[mi][ni][3];
            if (EPI == 1) { v0 *= alpha; v1 *= alpha; v2 *= alpha; v3 *= alpha; }
            if (EPI == 0 || EPI == 3) {
                float b0 = bias[nc], b1 = bias[nc + 1];
                v0 += b0; v1 += b1; v2 += b0; v3 += b1;
            }
            if (EPI == 3) {
                v0 = fmaxf(v0, 0.f); v1 = fmaxf(v1, 0.f);
                v2 = fmaxf(v2, 0.f); v3 = fmaxf(v3, 0.f);
            }
            if (EPI == 4 || EPI == 5) { v0 += bm0; v1 += bm0; v2 += bm8; v3 += bm8; }
            if (EPI == 4 || EPI == 6) {
                float2 r0 = *(const float2*)(Rb + (size_t)mr * ldc + nc);
                float2 r8 = *(const float2*)(Rb + (size_t)(mr + 8) * ldc + nc);
                v0 += r0.x; v1 += r0.y; v2 += r8.x; v3 += r8.y;
                *(float2*)(Cf + (size_t)mr * ldc + nc) = make_float2(v0, v1);
                *(float2*)(Cf + (size_t)(mr + 8) * ldc + nc) = make_float2(v2, v3);
            } else {
                *(__half2*)(Ch + (size_t)mr * ldc + nc) = __floats2half2_rn(v0, v1);
                *(__half2*)(Ch + (size_t)(mr + 8) * ldc + nc) = __floats2half2_rn(v2, v3);
            }
            if (EPI == 6) {
                int ml = wm * 64 + mi * 16 + g;
                int nl = wn * 32 + ni * 8 + tg * 2;
                smT[(nl + 0) * 136 + ml]     = __float2half(v0);
                smT[(nl + 1) * 136 + ml]     = __float2half(v1);
                smT[(nl + 0) * 136 + ml + 8] = __float2half(v2);
                smT[(nl + 1) * 136 + ml + 8] = __float2half(v3);
                rs0 += v0 + v1; rq0 += v0 * v0 + v1 * v1;
                rs8 += v2 + v3; rq8 += v2 * v2 + v3 * v3;
            }
        }
        if (EPI == 6) {
            // reduce over the 4 lanes (tg) sharing each row
            rs0 += __shfl_xor_sync(0xffffffffu, rs0, 1);
            rs0 += __shfl_xor_sync(0xffffffffu, rs0, 2);
            rq0 += __shfl_xor_sync(0xffffffffu, rq0, 1);
            rq0 += __shfl_xor_sync(0xffffffffu, rq0, 2);
            rs8 += __shfl_xor_sync(0xffffffffu, rs8, 1);
            rs8 += __shfl_xor_sync(0xffffffffu, rs8, 2);
            rq8 += __shfl_xor_sync(0xffffffffu, rq8, 1);
            rq8 += __shfl_xor_sync(0xffffffffu, rq8, 2);
            if (tg == 0) {
                int rl = wm * 64 + mi * 16 + g;
                pS [wn * 128 + rl]     = rs0;
                pS2[wn * 128 + rl]     = rq0;
                pS [wn * 128 + rl + 8] = rs8;
                pS2[wn * 128 + rl + 8] = rq8;
            }
        }
    }

    if (EPI == 6) {
        __syncthreads();
        // combine 4 wn-slots per row; write deterministic per-CTA partials
        if (tid < 128) {
            float s = pS[tid] + pS[128 + tid] + pS[256 + tid] + pS[384 + tid];
            float q = pS2[tid] + pS2[128 + tid] + pS2[256 + tid] + pS2[384 + tid];
            int slot = bz * 8 + blockIdx.x;
            ps [slot * CC + m0 + tid] = s;
            ps2[slot * CC + m0 + tid] = q;
        }
        // write xrt [hw][c]: coalesced rows
        __half* Xt = aux + (size_t)bz * sAux;
        #pragma unroll 8
        for (int it = 0; it < 32; it++) {
            int idx = it * 256 + tid;
            int row = idx >> 6, col = idx & 63;
            __half2 h = *(__half2*)(smT + row * 136 + col * 2);
            *(__half2*)(Xt + (size_t)(n0 + row) * CC + m0 + col * 2) = h;
        }
    }
}

// ---------------- elementwise / prep kernels ----------------
__global__ void bn_stats_kernel(const float* __restrict__ x,
                                const float* __restrict__ gamma,
                                const float* __restrict__ beta,
                                float* __restrict__ scale,
                                float* __restrict__ shift) {
    int c = blockIdx.x;
    int tid = threadIdx.x;
    float s = 0.f, s2 = 0.f;
    const float* xc = x + (size_t)c * HW;
    for (int b = 0; b < BB; b++) {
        const float* p = xc + (size_t)b * CC * HW;
        #pragma unroll 4
        for (int i = tid; i < HW; i += 256) {
            float v = p[i];
            s += v; s2 = fmaf(v, v, s2);
        }
    }
    __shared__ float ss[256], ss2[256];
    ss[tid] = s; ss2[tid] = s2;
    __syncthreads();
    for (int o = 128; o > 0; o >>= 1) {
        if (tid < o) { ss[tid] += ss[tid + o]; ss2[tid] += ss2[tid + o]; }
        __syncthreads();
    }
    if (tid == 0) {
        const float invN = 1.0f / (BB * HW);
        float mean = ss[0] * invN;
        float var  = ss2[0] * invN - mean * mean;
        float sc = gamma[c] * rsqrtf(var + 1e-5f);
        scale[c] = sc;
        shift[c] = beta[c] - mean * sc;
    }
}

// combine bn2 partials (256 slots) -> scale/shift
__global__ void bn2_combine(const float* __restrict__ ps, const float* __restrict__ ps2,
                            const float* __restrict__ gamma, const float* __restrict__ beta,
                            float* __restrict__ scale, float* __restrict__ shift) {
    int c = blockIdx.x * 256 + threadIdx.x;
    float s = 0.f, q = 0.f;
    for (int sl = 0; sl < 256; sl++) {
        s += ps[sl * CC + c];
        q += ps2[sl * CC + c];
    }
    const float invN = 1.0f / (BB * HW);
    float mean = s * invN;
    float var  = q * invN - mean * mean;
    float sc = gamma[c] * rsqrtf(var + 1e-5f);
    scale[c] = sc;
    shift[c] = beta[c] - mean * sc;
}

// x [c][hw] fp32 -> h^T [hw][c] half with bn1+relu
__global__ void bnT_kernel(const float* __restrict__ x, const float* __restrict__ sc,
                           const float* __restrict__ sh, __half* __restrict__ o) {
    __shared__ float t[32][33];
    int b = blockIdx.z;
    int hw0 = blockIdx.x * 32, c0 = blockIdx.y * 32;
    int tx = threadIdx.x, ty = threadIdx.y;
    const float* I = x + (size_t)b * CC * HW;
    __half* O = o + (size_t)b * HW * CC;
    #pragma unroll
    for (int j = 0; j < 32; j += 8) {
        int c = c0 + ty + j;
        float v = I[(size_t)c * HW + hw0 + tx];
        t[ty + j][tx] = fmaxf(fmaf(v, sc[c], sh[c]), 0.f);
    }
    __syncthreads();
    #pragma unroll
    for (int j = 0; j < 32; j += 8)
        O[(size_t)(hw0 + ty + j) * CC + c0 + tx] = __float2half(t[tx][ty + j]);
}

__global__ void round_half(const float* __restrict__ in, __half* __restrict__ out) {
    int i = blockIdx.x * 256 + threadIdx.x;
    float4 v = ((const float4*)in)[i];
    ((__half2*)out)[i * 2]     = __floats2half2_rn(v.x, v.y);
    ((__half2*)out)[i * 2 + 1] = __floats2half2_rn(v.z, v.w);
}

__global__ void w1_fold(const float* __restrict__ W1, const float* __restrict__ b1,
                        const float* __restrict__ sc, const float* __restrict__ sh,
                        __half* __restrict__ w1f, float* __restrict__ b1f) {
    int o = blockIdx.x;
    int tid = threadIdx.x;
    float acc = 0.f;
    for (int k = tid; k < CC; k += 256) {
        float w = W1[o * CC + k];
        acc = fmaf(w, sh[k], acc);
        w1f[o * CC + k] = __float2half(w * sc[k]);
    }
    __shared__ float r[256];
    r[tid] = acc; __syncthreads();
    for (int ofs = 128; ofs > 0; ofs >>= 1) {
        if (tid < ofs) r[tid] += r[tid + ofs];
        __syncthreads();
    }
    if (tid == 0) b1f[o] = b1[o] + r[0];
}

// row softmax over contiguous 1024-half rows of S^T, in place (axis = q)
__global__ void softmax_row(__half* __restrict__ S) {
    int row = blockIdx.x * 8 + (threadIdx.x >> 5);
    int lane = threadIdx.x & 31;
    __half2* p = (__half2*)(S + (size_t)row * HW);
    float f[32];
    #pragma unroll
    for (int i = 0; i < 16; i++) {
        float2 v = __half22float2(p[i * 32 + lane]);
        f[i * 2] = v.x; f[i * 2 + 1] = v.y;
    }
    float m = -3.0e38f;
    #pragma unroll
    for (int i = 0; i < 32; i++) m = fmaxf(m, f[i]);
    #pragma unroll
    for (int o = 16; o > 0; o >>= 1) m = fmaxf(m, __shfl_xor_sync(0xffffffffu, m, o));
    float s = 0.f;
    #pragma unroll
    for (int i = 0; i < 32; i++) { f[i] = fexp(f[i] - m); s += f[i]; }
    #pragma unroll
    for (int o = 16; o > 0; o >>= 1) s += __shfl_xor_sync(0xffffffffu, s, o);
    float inv = 1.0f / s;
    #pragma unroll
    for (int i = 0; i < 16; i++)
        p[i * 32 + lane] = __floats2half2_rn(f[i * 2] * inv, f[i * 2 + 1] * inv);
}

// ---------------- launcher ----------------
extern "C" void kernel_launch(void* const* d_in, const int* in_sizes, int n_in,
                              void* d_out, int out_size) {
    const float* x     = (const float*)d_in[0];
    const float* bn1_g = (const float*)d_in[1];
    const float* bn1_b = (const float*)d_in[2];
    const float* W_qkv = (const float*)d_in[3];
    const float* b_qkv = (const float*)d_in[4];
    const float* bn2_g = (const float*)d_in[5];
    const float* bn2_b = (const float*)d_in[6];
    const float* W1    = (const float*)d_in[7];
    const float* b1    = (const float*)d_in[8];
    const float* W2    = (const float*)d_in[9];
    const float* b2    = (const float*)d_in[10];
    float* out = (float*)d_out;

    __half *p_ht, *p_qkt, *p_v, *p_st, *p_xrt, *p_zt, *p_wqh, *p_w1f, *p_w2h;
    float *p_xr, *p_b1f, *p_s1, *p_h1, *p_s2, *p_h2, *p_ps, *p_ps2;
    cudaGetSymbolAddress((void**)&p_ht,  g_ht);
    cudaGetSymbolAddress((void**)&p_qkt, g_qkt);
    cudaGetSymbolAddress((void**)&p_v,   g_v);
    cudaGetSymbolAddress((void**)&p_st,  g_st);
    cudaGetSymbolAddress((void**)&p_xr,  g_xr);
    cudaGetSymbolAddress((void**)&p_xrt, g_xrt);
    cudaGetSymbolAddress((void**)&p_zt,  g_zt);
    cudaGetSymbolAddress((void**)&p_wqh, g_wqh);
    cudaGetSymbolAddress((void**)&p_w1f, g_w1f);
    cudaGetSymbolAddress((void**)&p_w2h, g_w2h);
    cudaGetSymbolAddress((void**)&p_b1f, g_b1f);
    cudaGetSymbolAddress((void**)&p_s1,  g_s1);
    cudaGetSymbolAddress((void**)&p_h1,  g_h1);
    cudaGetSymbolAddress((void**)&p_s2,  g_s2);
    cudaGetSymbolAddress((void**)&p_h2,  g_h2);
    cudaGetSymbolAddress((void**)&p_ps,  g_psum);
    cudaGetSymbolAddress((void**)&p_ps2, g_psum2);

    cudaFuncSetAttribute(hgemm<0>, cudaFuncAttributeMaxDynamicSharedMemorySize, SMB);
    cudaFuncSetAttribute(hgemm<1>, cudaFuncAttributeMaxDynamicSharedMemorySize, SMB);
    cudaFuncSetAttribute(hgemm<3>, cudaFuncAttributeMaxDynamicSharedMemorySize, SMB);
    cudaFuncSetAttribute(hgemm<4>, cudaFuncAttributeMaxDynamicSharedMemorySize, SMB);
    cudaFuncSetAttribute(hgemm<5>, cudaFuncAttributeMaxDynamicSharedMemorySize, SMB);
    cudaFuncSetAttribute(hgemm<6>, cudaFuncAttributeMaxDynamicSharedMemorySize, SMB);

    const long sX  = (long)CC * HW;
    const long sHT = (long)HW * CC;
    const long sQK = (long)HW * 128;
    const long sS  = (long)HW * HW;

    // prep: weights to half, bn1 stats, h^T
    round_half<<<OO * CC / 1024, 256>>>(W_qkv, p_wqh);
    round_half<<<CC * CC / 1024, 256>>>(W2, p_w2h);
    bn_stats_kernel<<<CC, 256>>>(x, bn1_g, bn1_b, p_s1, p_h1);
    bnT_kernel<<<dim3(HW / 32, CC / 32, BB), dim3(32, 8)>>>(x, p_s1, p_h1, p_ht);

    // qk[hw][128] = h^T . Wqk^T + b_qkv[0:128]
    hgemm<0><<<dim3(1, 8, BB), 256, SMB>>>(
        p_ht, p_wqh, p_qkt, CC, CC, CC, 128,
        sHT, 0L, sQK, b_qkv, nullptr, 0L, nullptr, 0L, nullptr, nullptr, 1.0f);

    // V[c][hw] = Wv . h + b_qkv[128+c]
    hgemm<5><<<dim3(8, 4, BB), 256, SMB>>>(
        p_wqh + 128 * CC, p_ht, p_v, CC, CC, CC, HW,
        0L, sHT, sX, b_qkv + 128, nullptr, 0L, nullptr, 0L, nullptr, nullptr, 1.0f);

    // S^T[k'][q] = (K . Q^T)/8
    hgemm<1><<<dim3(8, 8, BB), 256, SMB>>>(
        p_qkt + 64, p_qkt, p_st, DD, 128, 128, HW,
        sQK, sQK, sS, nullptr, nullptr, 0L, nullptr, 0L, nullptr, nullptr, 0.125f);

    // P^T row softmax in place
    softmax_row<<<BB * HW / 8, 256>>>(p_st);

    // xr = x + V . P ; fused: xrt (transposed half) + bn2 partial sums
    hgemm<6><<<dim3(8, 4, BB), 256, SMB>>>(
        p_v, p_st, p_xr, HW, HW, HW, HW,
        sX, sS, sX, nullptr, x, sX, p_xrt, sHT, p_ps, p_ps2, 1.0f);

    // bn2 combine + fold into W1
    bn2_combine<<<2, 256>>>(p_ps, p_ps2, bn2_g, bn2_b, p_s2, p_h2);
    w1_fold<<<CC, 256>>>(W1, b1, p_s2, p_h2, p_w1f, p_b1f);

    // z^T[hw][o] = relu(xr^T . W1'^T + b1')
    hgemm<3><<<dim3(4, 8, BB), 256, SMB>>>(
        p_xrt, p_w1f, p_zt, CC, CC, CC, CC,
        sHT, 0L, sHT, p_b1f, nullptr, 0L, nullptr, 0L, nullptr, nullptr, 1.0f);

    // out[c][hw] = xr + W2 . z + b2
    hgemm<4><<<dim3(8, 4, BB), 256, SMB>>>(
        p_w2h, p_zt, out, CC, CC, CC, HW,
        0L, sHT, sX, b2, p_xr, sX, nullptr, 0L, nullptr, nullptr, 1.0f);
}